// round 15
// baseline (speedup 1.0000x reference)
#include <cuda_runtime.h>

// Problem constants
#define BB 4
#define DDIM 64
#define HW (512*512)
#define KK 32

// Accum tiling: each tile = 2 channels (one pair) x CP pixels of one image.
#define T 256
#define CP 16384
#define NCHUNK (HW/CP)     // 16
#define NQ (DDIM/2)        // 32 channel pairs
#define NTILE (NCHUNK*NQ*BB)   // 2048 accum tiles
#define NCTILE (64*BB)         // 256 count tiles

// cp.async staging
#define SPX 2048               // pixels per stage
#define NSTG (CP/SPX)          // 8 stages per tile
#define RING 3                 // stage ring buffers
#define STG_F 4608             // floats per stage buffer: 2048(x)+2048(y)+512(lab bytes/4)
#define BIN_F (KK*T*3)         // 24576 floats of bin storage (s2 float2 + s_sq)

// Global scratch (no allocations; fully overwritten each call -> no zeroing)
__device__ float g_sum_part[BB*NQ*KK*2*NCHUNK];  // [(b,q,k)][ch][chunk]
__device__ float g_sq_part[BB*KK*NQ*NCHUNK];     // [(b,k)][q][chunk]
__device__ float g_cnt_part[BB*KK*64];           // [(b,k)][chunk64]
__device__ unsigned char g_lab8[BB*HW];          // packed labels (bytes)
__device__ float g_loss[BB];                     // per-image losses

// Device-wide sense-reversal barriers (replay-safe: gen increases monotonically)
__device__ unsigned g_bar_cnt[4];
__device__ unsigned g_bar_gen[4];

__device__ __forceinline__ void grid_barrier(int i, unsigned nb) {
    __syncthreads();
    if (threadIdx.x == 0) {
        __threadfence();
        unsigned gen = atomicAdd(&g_bar_gen[i], 0u);
        if (atomicAdd(&g_bar_cnt[i], 1u) == nb - 1u) {
            g_bar_cnt[i] = 0u;
            __threadfence();
            atomicAdd(&g_bar_gen[i], 1u);
        } else {
            while (atomicAdd(&g_bar_gen[i], 0u) == gen) __nanosleep(64);
        }
        __threadfence();
    }
    __syncthreads();
}

__device__ __forceinline__ unsigned su32(const void* p) {
    return (unsigned)__cvta_generic_to_shared(p);
}
__device__ __forceinline__ void cp16(unsigned dst, const void* src) {
    asm volatile("cp.async.cg.shared.global [%0], [%1], 16;" :: "r"(dst), "l"(src));
}
__device__ __forceinline__ void cp8(unsigned dst, const void* src) {
    asm volatile("cp.async.ca.shared.global [%0], [%1], 8;" :: "r"(dst), "l"(src));
}
__device__ __forceinline__ void cp_commit() {
    asm volatile("cp.async.commit_group;");
}
__device__ __forceinline__ void cp_wait2() {
    asm volatile("cp.async.wait_group 2;");
}

__global__ __launch_bounds__(T, 1) void fused_kernel(
    const float* __restrict__ feats, const int* __restrict__ labels,
    float* __restrict__ out, unsigned nb)
{
    extern __shared__ float smem[];
    const int t = threadIdx.x, lane = t & 31, w = t >> 5;
    const unsigned bid = blockIdx.x;

    // ---------------- Phase A: label histogram + byte-pack ----------------
    {
        float* s_cnt = smem;                    // KK*T floats
        for (unsigned tile = bid; tile < NCTILE; tile += nb) {
            const int chunk64 = tile & 63;
            const int b = tile >> 6;
            for (int i = t; i < KK*T; i += T) s_cnt[i] = 0.f;
            __syncthreads();
            const int4* L4 = (const int4*)(labels + (size_t)b * HW + (size_t)chunk64 * 4096);
            uchar4* P4 = (uchar4*)g_lab8 + ((size_t)b * HW >> 2) + (size_t)chunk64 * 1024;
#pragma unroll
            for (int g = 0; g < 4; ++g) {
                int4 L = L4[g*T + t];
                int x = L.x & 31, y = L.y & 31, z = L.z & 31, u = L.w & 31;
                s_cnt[x*T + t] += 1.f;
                s_cnt[y*T + t] += 1.f;
                s_cnt[z*T + t] += 1.f;
                s_cnt[u*T + t] += 1.f;
                P4[g*T + t] = make_uchar4((unsigned char)x, (unsigned char)y,
                                          (unsigned char)z, (unsigned char)u);
            }
            __syncthreads();
#pragma unroll
            for (int bbn = 0; bbn < 4; ++bbn) {
                const int bin = w*4 + bbn;
                float c = 0.f;
#pragma unroll
                for (int j = 0; j < T/32; ++j) c += s_cnt[bin*T + j*32 + lane];
#pragma unroll
                for (int off = 16; off; off >>= 1) c += __shfl_xor_sync(0xffffffffu, c, off);
                if (lane == 0) g_cnt_part[(b*KK + bin)*64 + chunk64] = c;
            }
            __syncthreads();
        }
    }
    grid_barrier(0, nb);

    // ---------------- Phase B: feature accumulation (cp.async staged) ----------------
    {
        float2* s2   = (float2*)smem;           // KK*T float2   (64 KB)
        float*  s_sq = smem + KK*T*2;           // KK*T floats   (32 KB)
        float*  stg  = smem + BIN_F;            // RING*STG_F floats (54 KB)

        for (unsigned tile = bid; tile < NTILE; tile += nb) {
            const int chunk = tile & (NCHUNK-1);
            const int q     = (tile >> 4) & (NQ-1);
            const int b     = tile >> 9;

            for (int i = t; i < KK*T; i += T) { s2[i] = make_float2(0.f, 0.f); s_sq[i] = 0.f; }
            __syncthreads();

            const size_t base = (size_t)(b*DDIM + q*2) * HW + (size_t)chunk * CP;
            const float* __restrict__ Gx = feats + base;
            const float* __restrict__ Gy = feats + base + HW;
            const unsigned char* __restrict__ GL = g_lab8 + (size_t)b * HW + (size_t)chunk * CP;

            // prologue: stage 0..2 into ring buffers 0..2
#pragma unroll
            for (int s = 0; s < RING; ++s) {
                float* bx = stg + s*STG_F;
                unsigned dx = su32(bx) + t*32u;                 // x: 32 B/thread
                cp16(dx,      Gx + s*SPX + t*8);
                cp16(dx + 16, Gx + s*SPX + t*8 + 4);
                unsigned dy = su32(bx + SPX) + t*32u;           // y
                cp16(dy,      Gy + s*SPX + t*8);
                cp16(dy + 16, Gy + s*SPX + t*8 + 4);
                unsigned dl = su32(bx + 2*SPX) + t*8u;          // labels: 8 B/thread
                cp8(dl, GL + s*SPX + t*8);
                cp_commit();
            }

#pragma unroll
            for (int s = 0; s < NSTG; ++s) {
                cp_wait2();            // groups pending <= 2 -> stage s landed
                __syncthreads();

                const int rb = s % RING;
                const float* bx = stg + rb*STG_F;
                const float* by = bx + SPX;
                const unsigned char* bl = (const unsigned char*)(bx + 2*SPX);

#pragma unroll
                for (int j = 0; j < SPX/T; ++j) {
                    const int px = j*T + t;
                    const float x = bx[px];
                    const float y = by[px];
                    const int bin = bl[px];
                    const int col = bin*T + t;
                    float2 a = s2[col];
                    a.x += x; a.y += y;
                    s2[col] = a;
                    s_sq[col] = fmaf(x, x, fmaf(y, y, s_sq[col]));
                }
                __syncthreads();       // all readers done before ring-buffer reuse

                if (s + RING < NSTG) {
                    const int sn = s + RING;
                    float* nbx = stg + rb*STG_F;
                    unsigned dx = su32(nbx) + t*32u;
                    cp16(dx,      Gx + sn*SPX + t*8);
                    cp16(dx + 16, Gx + sn*SPX + t*8 + 4);
                    unsigned dy = su32(nbx + SPX) + t*32u;
                    cp16(dy,      Gy + sn*SPX + t*8);
                    cp16(dy + 16, Gy + sn*SPX + t*8 + 4);
                    unsigned dl = su32(nbx + 2*SPX) + t*8u;
                    cp8(dl, GL + sn*SPX + t*8);
                }
                cp_commit();           // unconditional (possibly empty) -> wait_group 2 stays valid
            }
            __syncthreads();

            // flush: warp w reduces bins 4w..4w+3; non-atomic partial writes
#pragma unroll
            for (int bbn = 0; bbn < 4; ++bbn) {
                const int bin = w*4 + bbn;
                float ax = 0.f, ay = 0.f, sq = 0.f;
#pragma unroll
                for (int j = 0; j < T/32; ++j) {
                    const int col = bin*T + j*32 + lane;
                    float2 v = s2[col];
                    ax += v.x; ay += v.y;
                    sq += s_sq[col];
                }
#pragma unroll
                for (int off = 16; off; off >>= 1) {
                    ax += __shfl_xor_sync(0xffffffffu, ax, off);
                    ay += __shfl_xor_sync(0xffffffffu, ay, off);
                    sq += __shfl_xor_sync(0xffffffffu, sq, off);
                }
                if (lane == 0) {
                    const int sbase = ((b*NQ + q)*KK + bin)*(2*NCHUNK);
                    g_sum_part[sbase + chunk]          = ax;
                    g_sum_part[sbase + NCHUNK + chunk] = ay;
                    g_sq_part[((b*KK + bin)*NQ + q)*NCHUNK + chunk] = sq;
                }
            }
            __syncthreads();
        }
    }
    grid_barrier(1, nb);

    // ---------------- Phase C: per-image finalize (blocks 0..BB-1) ----------------
    if (bid < BB) {
        const int b = bid;
        float* s_mean = smem;                   // KK*65 floats (padded rows)
        float* s_cnt  = smem + KK*65;           // KK
        float* s_acc  = s_cnt + KK;             // 3: var, hinge, reg

        if (t < 3) s_acc[t] = 0.f;

#pragma unroll
        for (int bbn = 0; bbn < 4; ++bbn) {
            const int bin = w*4 + bbn;
            const float* p = &g_cnt_part[(b*KK + bin)*64];
            float cc = p[lane] + p[lane + 32];
#pragma unroll
            for (int off = 16; off; off >>= 1) cc += __shfl_xor_sync(0xffffffffu, cc, off);
            if (lane == 0) s_cnt[bin] = cc;
        }
        __syncthreads();

        for (int i = t; i < KK*DDIM; i += T) {
            const int k = i >> 6, d = i & 63, q = d >> 1, ch = d & 1;
            const float4* p4 = (const float4*)&g_sum_part[((b*NQ + q)*KK + k)*(2*NCHUNK) + ch*NCHUNK];
            float4 a = p4[0], b4 = p4[1], c4 = p4[2], d4 = p4[3];
            float s = ((a.x + a.y) + (a.z + a.w)) + ((b4.x + b4.y) + (b4.z + b4.w))
                    + ((c4.x + c4.y) + (c4.z + c4.w)) + ((d4.x + d4.y) + (d4.z + d4.w));
            s_mean[k*65 + d] = s / fmaxf(s_cnt[k], 1.f);
        }
        __syncthreads();

#pragma unroll
        for (int rep = 0; rep < 4; ++rep) {
            const int bin = w + rep*8;
            float m0 = s_mean[bin*65 + lane];
            float m1 = s_mean[bin*65 + lane + 32];
            float p = fmaf(m0, m0, m1*m1);
            const float4* q4 = (const float4*)&g_sq_part[(b*KK + bin)*NQ*NCHUNK]; // 512 floats
            float sq = 0.f;
#pragma unroll
            for (int j = 0; j < 4; ++j) {
                float4 v = q4[lane + 32*j];
                sq += (v.x + v.y) + (v.z + v.w);
            }
#pragma unroll
            for (int off = 16; off; off >>= 1) {
                p  += __shfl_xor_sync(0xffffffffu, p,  off);
                sq += __shfl_xor_sync(0xffffffffu, sq, off);
            }
            if (lane == 0) {
                float cc = s_cnt[bin];
                if (cc > 0.f) {
                    // sum ||f - mu||^2 = sumsq - cnt*||mu||^2 ; var_per = that / cnt
                    atomicAdd(&s_acc[0], (sq - cc*p) / cc);
                    atomicAdd(&s_acc[2], sqrtf(p));
                }
            }
        }

        for (int p = t; p < KK*KK; p += T) {
            const int i = p >> 5, j = p & 31;
            if (j > i && s_cnt[i] > 0.f && s_cnt[j] > 0.f) {
                float dsq = 0.f;
#pragma unroll
                for (int d = 0; d < DDIM; ++d) {
                    float df = s_mean[i*65 + d] - s_mean[j*65 + d];
                    dsq = fmaf(df, df, dsq);
                }
                float dist = sqrtf(dsq);
                if (dist < 3.0f) {            // 2*delta_d, delta_d = 1.5
                    float h = 3.0f - dist;
                    atomicAdd(&s_acc[1], h*h);
                }
            }
        }
        __syncthreads();

        if (t == 0) {
            float ncl = 0.f;
            for (int k = 0; k < KK; ++k) ncl += (s_cnt[k] > 0.f) ? 1.f : 0.f;
            float dist_loss = s_acc[1] / fmaxf(ncl - 1.f, 1.f);
            g_loss[b] = (s_acc[0] + dist_loss + 0.001f * s_acc[2]) / fmaxf(ncl, 1.f);
        }
    }
    grid_barrier(2, nb);

    // ---------------- Phase D: combine ----------------
    if (bid == 0 && t == 0)
        out[0] = (g_loss[0] + g_loss[1] + g_loss[2] + g_loss[3]) / (float)(BB + 1);
}

extern "C" void kernel_launch(void* const* d_in, const int* in_sizes, int n_in,
                              void* d_out, int out_size) {
    const float* feats  = (const float*)d_in[0];
    const int*   labels = (const int*)d_in[1];
    float*       out    = (float*)d_out;

    const int smem_bytes = (BIN_F + RING*STG_F) * (int)sizeof(float);  // 153600
    cudaFuncSetAttribute(fused_kernel, cudaFuncAttributeMaxDynamicSharedMemorySize,
                         smem_bytes);

    int dev = 0, sms = 148, occ = 0;
    cudaGetDevice(&dev);
    cudaDeviceGetAttribute(&sms, cudaDevAttrMultiProcessorCount, dev);
    cudaOccupancyMaxActiveBlocksPerMultiprocessor(&occ, fused_kernel, T, smem_bytes);
    if (occ < 1) occ = 1;
    unsigned nb = (unsigned)(sms * occ);
    if (nb > NTILE) nb = NTILE;

    fused_kernel<<<nb, T, smem_bytes>>>(feats, labels, out, nb);
}